// round 7
// baseline (speedup 1.0000x reference)
#include <cuda_runtime.h>
#include <cstdint>

#define NB    32
#define CIN   64
#define COUT  128
#define HDIM  128
#define WDIM  128
#define EPS   1e-5f

// Fragment-ordered weights, tf32 bits, contiguous per stage:
// stage s = kh*4 + icq (12 stages, 16 ic each)
// d = s*6144 + ((((kw*2)+ks)*2+wn)*32+lane)*16 + e
// e = nt*2+idx, lane = g*4+t
// value = w[ic = icq*16 + ks*8 + t + idx*4][oc = wn*64 + nt*8 + g][kh][kw]
__device__ float g_wt[73728];

__global__ void wt_transform_kernel(const float* __restrict__ w) {
    int d = blockIdx.x * blockDim.x + threadIdx.x;
    if (d >= 73728) return;
    int e    = d & 15;
    int lane = (d >> 4) & 31;
    int wn   = (d >> 9) & 1;
    int ks   = (d >> 10) & 1;
    int r2   = d >> 11;          // 0..35 : kw + 3*s
    int kw   = r2 % 3;
    int s    = r2 / 3;           // 0..11
    int kh   = s >> 2;
    int icq  = s & 3;
    int nt   = e >> 1;
    int idx  = e & 1;
    int g    = lane >> 2;
    int t    = lane & 3;
    int ic   = icq * 16 + ks * 8 + t + idx * 4;
    int oc   = wn * 64 + nt * 8 + g;
    float v = w[((ic * COUT + oc) * 3 + kh) * 3 + kw];
    uint32_t rb;
    asm("cvt.rna.tf32.f32 %0, %1;" : "=r"(rb) : "f"(v));
    g_wt[d] = __uint_as_float(rb);
}

// ---------------------------------------------------------------------------
// Helpers
// ---------------------------------------------------------------------------
__device__ __forceinline__ uint32_t f2tf32(float f) {
    uint32_t r;
    asm("cvt.rna.tf32.f32 %0, %1;" : "=r"(r) : "f"(f));
    return r;
}
__device__ __forceinline__ void cp_async16p(uint32_t saddr, const void* gaddr, bool pred) {
    int sz = pred ? 16 : 0;  // src-size 0 => zero-fill
    asm volatile("cp.async.cg.shared.global [%0], [%1], 16, %2;\n"
                 :: "r"(saddr), "l"(gaddr), "r"(sz));
}
// Zero-MUFU tanh-GELU (validated: rel_err identical to __expf version)
__device__ __forceinline__ float gelu_fast(float y) {
    float y2 = y * y;
    float v  = y * fmaf(-0.10294832f, y2, -2.3022083f);
    v = fminf(fmaxf(v, -126.0f), 126.0f);
    float r = v + 12582912.0f;
    float f = v - (r - 12582912.0f);
    int  ri = __float_as_int(r);
    float p = fmaf(f, 0.0096181291f, 0.0555041087f);
    p = fmaf(f, p, 0.2402265069f);
    p = fmaf(f, p, 0.6931471806f);
    p = fmaf(f, p, 1.0f);
    float w = __int_as_float(__float_as_int(p) + (ri << 23));
    float s = 1.0f + w;
    float x = __int_as_float(0x7EF311C3u - (uint32_t)__float_as_int(s));
    x = x * (2.0f - s * x);
    x = x * (2.0f - s * x);
    return y * x;
}
__device__ __forceinline__ void mma_tf32(float& d0, float& d1, float& d2, float& d3,
                                         uint32_t a0, uint32_t a1, uint32_t a2, uint32_t a3,
                                         uint32_t b0, uint32_t b1) {
    asm volatile(
        "mma.sync.aligned.m16n8k8.row.col.f32.tf32.tf32.f32 "
        "{%0,%1,%2,%3}, {%4,%5,%6,%7}, {%8,%9}, {%0,%1,%2,%3};\n"
        : "+f"(d0), "+f"(d1), "+f"(d2), "+f"(d3)
        : "r"(a0), "r"(a1), "r"(a2), "r"(a3), "r"(b0), "r"(b1));
}

// SMEM per buffer (floats):
//   Xs: 16 ic x 136 (raw fp32 x at j=4..131, zeros at j=0..3)
//   Wf: [kw3][ks2][wn2][lane32][20] (16 data + 4 pad; 20-fl stride: 16B-aligned
//       and conflict-free for LDS.128 — banks (lane*20)%32 distinct per phase)
#define XROW         136
#define XS_FLOATS    (16 * XROW)                // 2176
#define WROWF        20
#define WS_FLOATS    (3 * 2 * 2 * 32 * WROWF)   // 7680
#define STAGE_FLOATS (XS_FLOATS + WS_FLOATS)    // 9856
#define STAGE_BYTES  (STAGE_FLOATS * 4)         // 39424
#define SMEM_BYTES   (2 * STAGE_BYTES)          // 78848  -> 2 CTAs/SM

// ---------------------------------------------------------------------------
// Fused kernel: CTA = 1 pixel row (M=128) x 128 oc. 8 warps (4m x 2n),
// warp tile 32x64. 12 double-buffered stages of K=48 (kh x 16-ic quarter).
// 2 CTAs/SM: phase-shifted CTAs fill each other's sync/producer bubbles.
// ---------------------------------------------------------------------------
__global__ void __launch_bounds__(256, 2)
fused_kernel(const float* __restrict__ x,
             const float* __restrict__ bias,
             const float* __restrict__ gamma,
             const float* __restrict__ beta,
             float* __restrict__ out) {
    extern __shared__ float smf[];
    const uint32_t smem_u = (uint32_t)__cvta_generic_to_shared(smf);
    const int tid  = threadIdx.x;
    const int nimg = blockIdx.y;
    const int oh   = blockIdx.x;

    const int lane = tid & 31;
    const int warp = tid >> 5;
    const int g    = lane >> 2;
    const int t    = lane & 3;
    const int wm   = warp & 3;    // 4 m-warps
    const int wn   = warp >> 2;   // 2 n-warps
    const int mcol = wm * 32;
    const int nb   = wn * 64;

    // Zero left-pad cols j=0..3 of Xs (2 bufs x 16 rows x 4 = 128 writes)
    if (tid < 128) {
        int b   = tid >> 6;
        int row = (tid >> 2) & 15;
        int j   = tid & 3;
        smf[b * STAGE_FLOATS + row * XROW + j] = 0.0f;
    }

    // Stage producer: all cp.async (X may ZFILL when ih < 0)
    auto issue_stage = [&](int s, int buf) {
        const int kh  = s >> 2;
        const int icq = s & 3;
        const int ih  = oh - kh;
        const bool ok = (ih >= 0);
        const int ihc = ok ? ih : 0;
        const uint32_t base = smem_u + (uint32_t)(buf * STAGE_BYTES);
        // X: 512 x 16B chunks (16 rows x 32)
        #pragma unroll
        for (int k = 0; k < 2; ++k) {
            int c  = tid + k * 256;
            int i  = c >> 5;
            int cc = c & 31;
            const float* gp = x +
                ((((size_t)(nimg * CIN + icq * 16 + i)) * HDIM + ihc) << 7) + cc * 4;
            cp_async16p(base + (uint32_t)((i * XROW + 4 + cc * 4) * 4), gp, ok);
        }
        // W: 1536 x 16B chunks (384 fragment-rows x 4)
        const float* wsrc = g_wt + s * 6144;
        #pragma unroll
        for (int k = 0; k < 6; ++k) {
            int c    = tid + k * 256;
            int r    = c >> 2;
            int part = c & 3;
            cp_async16p(base + (uint32_t)((XS_FLOATS + r * WROWF + part * 4) * 4),
                        wsrc + c * 4, true);
        }
        asm volatile("cp.async.commit_group;\n");
    };

    float acc[2][8][4];
    #pragma unroll
    for (int mt = 0; mt < 2; ++mt)
        #pragma unroll
        for (int nt = 0; nt < 8; ++nt)
            #pragma unroll
            for (int q = 0; q < 4; ++q) acc[mt][nt][q] = 0.0f;

    issue_stage(0, 0);

    #pragma unroll 1
    for (int s = 0; s < 12; ++s) {
        const int buf = s & 1;
        asm volatile("cp.async.wait_group 0;\n");
        __syncthreads();
        if (s + 1 < 12) issue_stage(s + 1, buf ^ 1);  // overlaps with MMA below

        const float* Xb = smf + buf * STAGE_FLOATS;
        const float* Wf = Xb + XS_FLOATS;

        #pragma unroll
        for (int kw = 0; kw < 3; ++kw) {
            const int jb = mcol + 4 - kw + g;
            #pragma unroll
            for (int ks = 0; ks < 2; ++ks) {
                const float4* wp = (const float4*)(Wf +
                    (size_t)(((kw * 2 + ks) * 2 + wn) * 32 + lane) * WROWF);
                float4 q0 = wp[0], q1 = wp[1], q2 = wp[2], q3 = wp[3];
                const int kr = ks * 8 + t;
                uint32_t a[2][4];
                #pragma unroll
                for (int mt = 0; mt < 2; ++mt) {
                    int jj = jb + mt * 16;
                    a[mt][0] = f2tf32(Xb[kr * XROW + jj]);
                    a[mt][1] = f2tf32(Xb[kr * XROW + jj + 8]);
                    a[mt][2] = f2tf32(Xb[(kr + 4) * XROW + jj]);
                    a[mt][3] = f2tf32(Xb[(kr + 4) * XROW + jj + 8]);
                }
                float bf[16] = {q0.x, q0.y, q0.z, q0.w, q1.x, q1.y, q1.z, q1.w,
                                q2.x, q2.y, q2.z, q2.w, q3.x, q3.y, q3.z, q3.w};
                #pragma unroll
                for (int mt = 0; mt < 2; ++mt)
                    #pragma unroll
                    for (int nt = 0; nt < 8; ++nt)
                        mma_tf32(acc[mt][nt][0], acc[mt][nt][1], acc[mt][nt][2], acc[mt][nt][3],
                                 a[mt][0], a[mt][1], a[mt][2], a[mt][3],
                                 __float_as_uint(bf[2 * nt]), __float_as_uint(bf[2 * nt + 1]));
            }
        }
        __syncthreads();
    }

    // ---------------- Epilogue: bias + GELU + per-pixel GroupNorm ----------
    float b_r[16];
    #pragma unroll
    for (int nt = 0; nt < 8; ++nt)
        #pragma unroll
        for (int j = 0; j < 2; ++j)
            b_r[nt * 2 + j] = __ldg(bias + nb + nt * 8 + 2 * t + j);

    const size_t out_img = (size_t)nimg * COUT * HDIM * WDIM;

    #pragma unroll
    for (int mt = 0; mt < 2; ++mt) {
        #pragma unroll
        for (int h = 0; h < 2; ++h) {
            int ow = mcol + mt * 16 + g + 8 * h;
            float gv[16];
            #pragma unroll
            for (int nt = 0; nt < 8; ++nt)
                #pragma unroll
                for (int j = 0; j < 2; ++j) {
                    int q = nt * 2 + j;
                    gv[q] = gelu_fast(acc[mt][nt][2 * h + j] + b_r[q]);
                }
            // Each 16-channel group lives inside one lane-quad: 2 shfl pairs
            #pragma unroll
            for (int g2 = 0; g2 < 4; ++g2) {
                float s1 = gv[4 * g2] + gv[4 * g2 + 1] + gv[4 * g2 + 2] + gv[4 * g2 + 3];
                float s2 = fmaf(gv[4 * g2], gv[4 * g2],
                           fmaf(gv[4 * g2 + 1], gv[4 * g2 + 1],
                           fmaf(gv[4 * g2 + 2], gv[4 * g2 + 2],
                                gv[4 * g2 + 3] * gv[4 * g2 + 3])));
                s1 += __shfl_xor_sync(0xffffffffu, s1, 1);
                s2 += __shfl_xor_sync(0xffffffffu, s2, 1);
                s1 += __shfl_xor_sync(0xffffffffu, s1, 2);
                s2 += __shfl_xor_sync(0xffffffffu, s2, 2);
                float mean = s1 * (1.0f / 16.0f);
                float var  = fmaf(s2, 1.0f / 16.0f, -mean * mean);
                float rstd = rsqrtf(var + EPS);
                #pragma unroll
                for (int u = 0; u < 4; ++u) {
                    int q  = 4 * g2 + u;
                    int nt = q >> 1;
                    int j  = q & 1;
                    int oc = nb + nt * 8 + 2 * t + j;
                    float val = fmaf((gv[q] - mean) * rstd, __ldg(gamma + oc), __ldg(beta + oc));
                    out[out_img + (size_t)oc * (HDIM * WDIM) + oh * WDIM + ow] = val;
                }
            }
        }
    }
}

// ---------------------------------------------------------------------------
// Launch
// ---------------------------------------------------------------------------
extern "C" void kernel_launch(void* const* d_in, const int* in_sizes, int n_in,
                              void* d_out, int out_size) {
    const float* x  = (const float*)d_in[0];
    const float* w  = (const float*)d_in[1];
    const float* b  = (const float*)d_in[2];
    const float* gw = (const float*)d_in[3];
    const float* gb = (const float*)d_in[4];
    float* out = (float*)d_out;

    wt_transform_kernel<<<(73728 + 255) / 256, 256>>>(w);

    cudaFuncSetAttribute(fused_kernel,
                         cudaFuncAttributeMaxDynamicSharedMemorySize, SMEM_BYTES);
    dim3 grid(HDIM, NB);  // 128 rows x 32 images = 4096 CTAs
    fused_kernel<<<grid, 256, SMEM_BYTES>>>(x, b, gw, gb, out);
}